// round 5
// baseline (speedup 1.0000x reference)
#include <cuda_runtime.h>
#include <cstdint>

#define BB    64
#define CIN   64
#define HH    56
#define WW    56
#define CHN   512
#define IN_DIM (CIN*HH*WW)      // 200704
#define NKEEP 128
#define SPLITK 64
#define KC (IN_DIM/SPLITK)      // 3136
#define SPAT (HH*WW)            // 3136
#define NTILES 25               // ceil(3136/128)
#define KCHUNKS 18              // 9 taps * 2 ci-halves of 32

// ---------------- small helpers ----------------
__device__ __forceinline__ float to_tf32(float f) {
    uint32_t u; asm("cvt.rna.tf32.f32 %0, %1;" : "=r"(u) : "f"(f));
    return __uint_as_float(u);
}
// tf32 tensor-core MMA (sm_80+ baseline PTX -> valid on base sm_103 target)
__device__ __forceinline__ void mma_tf32(float* c, const uint32_t* a, const uint32_t* b) {
    asm volatile(
        "mma.sync.aligned.m16n8k8.row.col.f32.tf32.tf32.f32 "
        "{%0,%1,%2,%3}, {%4,%5,%6,%7}, {%8,%9}, {%0,%1,%2,%3};"
        : "+f"(c[0]), "+f"(c[1]), "+f"(c[2]), "+f"(c[3])
        : "r"(a[0]), "r"(a[1]), "r"(a[2]), "r"(a[3]), "r"(b[0]), "r"(b[1]));
}

// ---------------- scratch (__device__ globals; no allocs allowed) ----------
__device__ float g_partial[SPLITK * BB * CHN];  // 8 MB
__device__ float g_scores[BB * CHN];
__device__ int   g_idx[BB * NKEEP];
__device__ float g_xt[(size_t)BB * SPAT * CIN];   // x channels-last, tf32-rounded
__device__ float g_bw[(size_t)BB * NKEEP * 576];  // gathered weights [b][n][tap*64+ci]

// ---------------------------------------------------------------------------
// Kernel 1: router GEMM partials on tensor cores, tf32x3 (hi/lo split) for
// ~fp32 accuracy. scores[m,n] = sum_k x[m,k]*rw[n,k].
// Grid (8 n-tiles, 64 k-splits); block 256 thr = 8 warps (2m x 4n);
// tile M=64 x N=64, K-chunks of 32. hi/lo computed in regs during staging.
// ---------------------------------------------------------------------------
__global__ __launch_bounds__(256) void router_tc(const float* __restrict__ x,
                                                 const float* __restrict__ rw) {
    // fragment-native layouts:
    // sA*[(mtile*4 + k8)*32 + lane][4 slots], sB*[(ntile*4 + k8)*32 + lane][2 slots]
    __shared__ __align__(16) float sAh[4 * 4 * 32 * 4];   // 8 KB
    __shared__ __align__(16) float sAl[4 * 4 * 32 * 4];   // 8 KB
    __shared__ __align__(16) float sBh[8 * 4 * 32 * 2];   // 8 KB
    __shared__ __align__(16) float sBl[8 * 4 * 32 * 2];   // 8 KB

    const int ntile = blockIdx.x;    // 0..7
    const int sk    = blockIdx.y;    // 0..63
    const int tid  = threadIdx.x;
    const int lane = tid & 31;
    const int wid  = tid >> 5;
    const int wm   = wid & 1;        // m half (32 rows)
    const int wn   = wid >> 1;       // n quarter (16 cols)

    // staging role: row = tid>>2 (0..63), k-segment of 8
    const int row = tid >> 2;
    const int ksg = (tid & 3) * 8;
    const int k8s = tid & 3;         // k8 index of this segment
    const float* ap = x  + (size_t)row * IN_DIM + (size_t)sk * KC + ksg;
    const float* bp = rw + (size_t)(ntile * 64 + row) * IN_DIM + (size_t)sk * KC + ksg;

    // scatter bases
    const int a_mt = row >> 4;
    const int a_r  = row & 15;
    const int a_laneb = (a_r & 7) << 2;
    const int a_slotb = a_r >> 3;
    const int b_nt  = row >> 3;
    const int b_nin = row & 7;

    float acc[2][2][4];
#pragma unroll
    for (int mt = 0; mt < 2; mt++)
#pragma unroll
        for (int nt = 0; nt < 2; nt++)
#pragma unroll
            for (int r = 0; r < 4; r++) acc[mt][nt][r] = 0.f;

    for (int k0 = 0; k0 < KC; k0 += 32) {
        float av[8], bv[8];
        *(float4*)&av[0] = *(const float4*)(ap + k0);
        *(float4*)&av[4] = *(const float4*)(ap + k0 + 4);
        *(float4*)&bv[0] = *(const float4*)(bp + k0);
        *(float4*)&bv[4] = *(const float4*)(bp + k0 + 4);

        __syncthreads();   // previous compute done before overwrite
#pragma unroll
        for (int i = 0; i < 8; i++) {
            float vh = to_tf32(av[i]);
            float vl = to_tf32(av[i] - vh);
            int idx = ((((a_mt << 2) | k8s) << 5) | (a_laneb | (i & 3))) * 4
                      + (a_slotb | ((i >> 2) << 1));
            sAh[idx] = vh; sAl[idx] = vl;
            float wh = to_tf32(bv[i]);
            float wl = to_tf32(bv[i] - wh);
            int jdx = ((((b_nt << 2) | k8s) << 5) | ((b_nin << 2) | (i & 3))) * 2
                      + (i >> 2);
            sBh[jdx] = wh; sBl[jdx] = wl;
        }
        __syncthreads();

#pragma unroll
        for (int k8 = 0; k8 < 4; k8++) {
            uint32_t ah[2][4], al[2][4];
#pragma unroll
            for (int mt = 0; mt < 2; mt++) {
                int base = ((((wm * 2 + mt) << 2) | k8) << 5 | lane) * 4;
                float4 vh = *(const float4*)&sAh[base];
                float4 vl = *(const float4*)&sAl[base];
                ah[mt][0] = __float_as_uint(vh.x); ah[mt][1] = __float_as_uint(vh.y);
                ah[mt][2] = __float_as_uint(vh.z); ah[mt][3] = __float_as_uint(vh.w);
                al[mt][0] = __float_as_uint(vl.x); al[mt][1] = __float_as_uint(vl.y);
                al[mt][2] = __float_as_uint(vl.z); al[mt][3] = __float_as_uint(vl.w);
            }
            uint32_t bh[2][2], bl[2][2];
#pragma unroll
            for (int nt = 0; nt < 2; nt++) {
                int base = ((((wn * 2 + nt) << 2) | k8) << 5 | lane) * 2;
                float2 vh = *(const float2*)&sBh[base];
                float2 vl = *(const float2*)&sBl[base];
                bh[nt][0] = __float_as_uint(vh.x); bh[nt][1] = __float_as_uint(vh.y);
                bl[nt][0] = __float_as_uint(vl.x); bl[nt][1] = __float_as_uint(vl.y);
            }
#pragma unroll
            for (int mt = 0; mt < 2; mt++)
#pragma unroll
                for (int nt = 0; nt < 2; nt++) {
                    mma_tf32(acc[mt][nt], ah[mt], bh[nt]);
                    mma_tf32(acc[mt][nt], ah[mt], bl[nt]);
                    mma_tf32(acc[mt][nt], al[mt], bh[nt]);
                }
        }
    }

    // store partials: c0:(r,c) c1:(r,c+1) c2:(r+8,c) c3:(r+8,c+1)
    const int row0 = lane >> 2;
    const int col0 = (lane & 3) * 2;
#pragma unroll
    for (int mt = 0; mt < 2; mt++) {
#pragma unroll
        for (int nt = 0; nt < 2; nt++) {
            int m = wm * 32 + mt * 16 + row0;
            int n = ntile * 64 + wn * 16 + nt * 8 + col0;
            float* p0 = &g_partial[((size_t)sk * BB + m) * CHN + n];
            p0[0] = acc[mt][nt][0];
            p0[1] = acc[mt][nt][1];
            float* p1 = p0 + 8 * CHN;
            p1[0] = acc[mt][nt][2];
            p1[1] = acc[mt][nt][3];
        }
    }
}

// ---------------------------------------------------------------------------
// Kernel 2: reduce split-K partials + bias
// ---------------------------------------------------------------------------
__global__ void reduce_scores(const float* __restrict__ rb) {
    int t = blockIdx.x * 256 + threadIdx.x;
    int m = t >> 9;
    int n = t & 511;
    float sum = rb[n];
    for (int s = 0; s < SPLITK; s++)
        sum += g_partial[((size_t)s * BB + m) * CHN + n];
    g_scores[t] = sum;
}

// ---------------------------------------------------------------------------
// Kernel 3: per-row stable top-128 by |score| (jax tie rule), sorted indices
// ---------------------------------------------------------------------------
__global__ __launch_bounds__(CHN) void select_topk() {
    __shared__ float sa[CHN];
    __shared__ unsigned char keep[CHN];
    const int m = blockIdx.x;
    const int i = threadIdx.x;
    float v = fabsf(g_scores[m * CHN + i]);
    sa[i] = v;
    __syncthreads();
    int rank = 0;
    for (int j = 0; j < CHN; j++) {
        float u = sa[j];
        rank += (u > v) || (u == v && j < i);
    }
    keep[i] = (rank < NKEEP) ? 1 : 0;
    __syncthreads();
    if (keep[i]) {
        int pos = 0;
        for (int j = 0; j < i; j++) pos += keep[j];
        g_idx[m * NKEEP + pos] = i;
    }
}

// ---------------------------------------------------------------------------
// Kernel T: transpose x to channels-last, rounding to tf32.
// ---------------------------------------------------------------------------
__global__ __launch_bounds__(256) void transpose_x(const float* __restrict__ x) {
    __shared__ float tile[32][33];
    const int s0 = blockIdx.x * 32;
    const int c0 = blockIdx.y * 32;
    const int b  = blockIdx.z;
    const int tx = threadIdx.x;
    const int ty = threadIdx.y;
#pragma unroll
    for (int k = 0; k < 4; k++) {
        int ci = c0 + ty + k * 8;
        tile[ty + k * 8][tx] = x[((size_t)b * CIN + ci) * SPAT + s0 + tx];
    }
    __syncthreads();
#pragma unroll
    for (int k = 0; k < 4; k++) {
        int srow = s0 + ty + k * 8;
        g_xt[((size_t)b * SPAT + srow) * CIN + c0 + tx] = to_tf32(tile[tx][ty + k * 8]);
    }
}

// ---------------------------------------------------------------------------
// Kernel G: gather selected-channel weights per sample, K-reordered + tf32.
// ---------------------------------------------------------------------------
__global__ __launch_bounds__(192) void gather_w(const float* __restrict__ cw) {
    const int n = blockIdx.x;
    const int b = blockIdx.y;
    const int c = g_idx[b * NKEEP + n];
    const float* src = cw + (size_t)c * 576;
    float* dst = g_bw + ((size_t)(b * NKEEP + n)) * 576;
    for (int t = threadIdx.x; t < 576; t += 192)
        dst[t] = to_tf32(src[(t & 63) * 9 + (t >> 6)]);
}

// ---------------------------------------------------------------------------
// Kernel 4: conv as implicit GEMM on tensor cores (tf32 m16n8k8) — unchanged.
// ---------------------------------------------------------------------------
__global__ __launch_bounds__(256) void conv_mma(const float* __restrict__ cb,
                                                float* __restrict__ out) {
    __shared__ __align__(16) float sA[8 * 4 * 32 * 4];    // 16 KB
    __shared__ __align__(16) float sB[16 * 4 * 32 * 2];   // 16 KB
    __shared__ float sbias[NKEEP];

    const int tid  = threadIdx.x;
    const int lane = tid & 31;
    const int wid  = tid >> 5;
    const int wm   = wid & 1;
    const int wn   = wid >> 1;
    const int t = blockIdx.x;
    const int b = blockIdx.y;

    if (tid < NKEEP) sbias[tid] = cb[g_idx[b * NKEEP + tid]];

    const int m_row = tid >> 1;
    const int ks    = (tid & 1) * 16;
    const int s  = t * 128 + m_row;
    const int hh = s / WW;
    const int ww = s % WW;
    const float* bsrc = g_bw + ((size_t)(b * NKEEP + m_row)) * 576 + ks;

    const int a_mt  = m_row >> 4;
    const int a_row = m_row & 15;
    const int a_laneb = (a_row & 7) << 2;
    const int a_slotb = a_row >> 3;
    const int b_nt  = m_row >> 3;
    const int b_nin = m_row & 7;

    float acc[4][4][4];
#pragma unroll
    for (int mt = 0; mt < 4; mt++)
#pragma unroll
        for (int nt = 0; nt < 4; nt++)
#pragma unroll
            for (int r = 0; r < 4; r++) acc[mt][nt][r] = 0.f;

    for (int kc = 0; kc < KCHUNKS; kc++) {
        const int tap = kc >> 1;
        const int hc  = kc & 1;
        const int hp = hh + tap / 3 - 1;
        const int wp = ww + tap % 3 - 1;
        const bool valid = (s < SPAT) && ((unsigned)hp < (unsigned)HH) &&
                           ((unsigned)wp < (unsigned)WW);
        float av[16], bv[16];
        if (valid) {
            const float* asrc = g_xt + (((size_t)b * SPAT + hp * WW + wp) << 6) + hc * 32 + ks;
#pragma unroll
            for (int i = 0; i < 4; i++) *(float4*)&av[i * 4] = *(const float4*)(asrc + i * 4);
        } else {
#pragma unroll
            for (int i = 0; i < 16; i++) av[i] = 0.f;
        }
#pragma unroll
        for (int i = 0; i < 4; i++) *(float4*)&bv[i * 4] = *(const float4*)(bsrc + kc * 32 + i * 4);

        __syncthreads();
#pragma unroll
        for (int i = 0; i < 16; i++) {
            int k  = ks + i;
            int k8 = k >> 3, col = k & 7;
            int lanei = a_laneb | (col & 3);
            int sloti = a_slotb | ((col >> 2) << 1);
            sA[((((a_mt << 2) | k8) << 5) | lanei) * 4 + sloti] = av[i];
        }
#pragma unroll
        for (int i = 0; i < 16; i++) {
            int k  = ks + i;
            int k8 = k >> 3, kin = k & 7;
            int lanei = (b_nin << 2) | (kin & 3);
            int sloti = kin >> 2;
            sB[((((b_nt << 2) | k8) << 5) | lanei) * 2 + sloti] = bv[i];
        }
        __syncthreads();

#pragma unroll
        for (int k8 = 0; k8 < 4; k8++) {
            uint32_t af[4][4];
#pragma unroll
            for (int mt = 0; mt < 4; mt++) {
                float4 v = *(const float4*)&sA[((((wm * 4 + mt) << 2) | k8) << 5 | lane) * 4];
                af[mt][0] = __float_as_uint(v.x); af[mt][1] = __float_as_uint(v.y);
                af[mt][2] = __float_as_uint(v.z); af[mt][3] = __float_as_uint(v.w);
            }
            uint32_t bf[4][2];
#pragma unroll
            for (int nt = 0; nt < 4; nt++) {
                float2 v = *(const float2*)&sB[((((wn * 4 + nt) << 2) | k8) << 5 | lane) * 2];
                bf[nt][0] = __float_as_uint(v.x); bf[nt][1] = __float_as_uint(v.y);
            }
#pragma unroll
            for (int mt = 0; mt < 4; mt++)
#pragma unroll
                for (int nt = 0; nt < 4; nt++)
                    mma_tf32(acc[mt][nt], af[mt], bf[nt]);
        }
    }

    const int row0 = lane >> 2;
    const int col0 = (lane & 3) * 2;
#pragma unroll
    for (int mt = 0; mt < 4; mt++) {
#pragma unroll
        for (int nt = 0; nt < 4; nt++) {
            int n  = wn * 32 + nt * 8 + col0;
            int sr = t * 128 + wm * 64 + mt * 16 + row0;
            float b0 = sbias[n], b1 = sbias[n + 1];
            float* op0 = out + ((size_t)b * NKEEP + n) * SPAT;
            float* op1 = op0 + SPAT;
            if (sr < SPAT) {
                op0[sr] = acc[mt][nt][0] + b0;
                op1[sr] = acc[mt][nt][1] + b1;
            }
            if (sr + 8 < SPAT) {
                op0[sr + 8] = acc[mt][nt][2] + b0;
                op1[sr + 8] = acc[mt][nt][3] + b1;
            }
        }
    }
}

// ---------------------------------------------------------------------------
extern "C" void kernel_launch(void* const* d_in, const int* in_sizes, int n_in,
                              void* d_out, int out_size) {
    const float* x  = (const float*)d_in[0];   // [64,64,56,56]
    const float* cw = (const float*)d_in[1];   // [512,64,3,3]
    const float* cb = (const float*)d_in[2];   // [512]
    const float* rw = (const float*)d_in[3];   // [512,200704]
    const float* rb = (const float*)d_in[4];   // [512]
    float* out = (float*)d_out;                // [64,128,56,56]

    router_tc<<<dim3(8, SPLITK), 256>>>(x, rw);
    transpose_x<<<dim3(SPAT / 32, CIN / 32, BB), dim3(32, 8)>>>(x);
    reduce_scores<<<(BB * CHN) / 256, 256>>>(rb);
    select_topk<<<BB, CHN>>>();
    gather_w<<<dim3(NKEEP, BB), 192>>>(cw);
    conv_mma<<<dim3(NTILES, BB), 256>>>(cb, out);
}

// round 6
// speedup vs baseline: 1.0966x; 1.0966x over previous
#include <cuda_runtime.h>
#include <cstdint>

#define BB    64
#define CIN   64
#define HH    56
#define WW    56
#define CHN   512
#define IN_DIM (CIN*HH*WW)      // 200704
#define NKEEP 128
#define SPLITK 64
#define KC (IN_DIM/SPLITK)      // 3136
#define SPAT (HH*WW)            // 3136
#define NTILES 25               // ceil(3136/128)
#define KCHUNKS 18              // 9 taps * 2 ci-halves of 32

typedef unsigned long long ull;

// ---------------- small helpers ----------------
__device__ __forceinline__ ull pack2(float lo, float hi) {
    ull r; asm("mov.b64 %0, {%1,%2};" : "=l"(r) : "f"(lo), "f"(hi)); return r;
}
__device__ __forceinline__ float2 unpack2(ull v) {
    float2 f; asm("mov.b64 {%0,%1}, %2;" : "=f"(f.x), "=f"(f.y) : "l"(v)); return f;
}
__device__ __forceinline__ void fma2(ull& d, ull a, ull b) {
    asm("fma.rn.f32x2 %0, %1, %2, %0;" : "+l"(d) : "l"(a), "l"(b));
}
__device__ __forceinline__ float to_tf32(float f) {
    uint32_t u; asm("cvt.rna.tf32.f32 %0, %1;" : "=r"(u) : "f"(f));
    return __uint_as_float(u);
}
__device__ __forceinline__ void mma_tf32(float* c, const uint32_t* a, const uint32_t* b) {
    asm volatile(
        "mma.sync.aligned.m16n8k8.row.col.f32.tf32.tf32.f32 "
        "{%0,%1,%2,%3}, {%4,%5,%6,%7}, {%8,%9}, {%0,%1,%2,%3};"
        : "+f"(c[0]), "+f"(c[1]), "+f"(c[2]), "+f"(c[3])
        : "r"(a[0]), "r"(a[1]), "r"(a[2]), "r"(a[3]), "r"(b[0]), "r"(b[1]));
}

// ---------------- scratch ----------------
__device__ float g_partial[SPLITK * BB * CHN];  // 8 MB
__device__ int   g_idx[BB * NKEEP];
__device__ float g_xt[(size_t)BB * SPAT * CIN];   // x channels-last, tf32-rounded
__device__ float g_bw[(size_t)BB * NKEEP * 576];  // gathered weights [b][n][tap*64+ci]

// ---------------------------------------------------------------------------
// Kernel T (idx 0): transpose x to channels-last, rounding to tf32.
// ---------------------------------------------------------------------------
__global__ __launch_bounds__(256) void transpose_x(const float* __restrict__ x) {
    __shared__ float tile[32][33];
    const int s0 = blockIdx.x * 32;
    const int c0 = blockIdx.y * 32;
    const int b  = blockIdx.z;
    const int tx = threadIdx.x;
    const int ty = threadIdx.y;
#pragma unroll
    for (int k = 0; k < 4; k++) {
        int ci = c0 + ty + k * 8;
        tile[ty + k * 8][tx] = x[((size_t)b * CIN + ci) * SPAT + s0 + tx];
    }
    __syncthreads();
#pragma unroll
    for (int k = 0; k < 4; k++) {
        int srow = s0 + ty + k * 8;
        g_xt[((size_t)b * SPAT + srow) * CIN + c0 + tx] = to_tf32(tile[tx][ty + k * 8]);
    }
}

// ---------------------------------------------------------------------------
// Kernel 1 (idx 1): router GEMM partials via packed f32x2 FMA (proven R4 ver).
// ---------------------------------------------------------------------------
__global__ __launch_bounds__(256) void router_gemm(const float* __restrict__ x,
                                                   const float* __restrict__ rw) {
    const int nt = blockIdx.x;
    const int s  = blockIdx.y;
    __shared__ __align__(16) ull   As2[16][64];
    __shared__ __align__(16) float Bs[16][68];

    const int tid = threadIdx.x;
    const int tx = tid & 15;
    const int ty = tid >> 4;
    const int lm = tid >> 2;
    const int lk = (tid & 3) * 4;

    const float* xp = x  + (size_t)lm * IN_DIM + (size_t)s * KC;
    const float* wp = rw + (size_t)(nt * 64 + lm) * IN_DIM + (size_t)s * KC;

    ull acc[4][2];
#pragma unroll
    for (int i = 0; i < 4; i++) { acc[i][0] = 0ull; acc[i][1] = 0ull; }

    for (int k0 = 0; k0 < KC; k0 += 16) {
        float4 av = *(const float4*)(xp + k0 + lk);
        float4 bv = *(const float4*)(wp + k0 + lk);
        __syncthreads();
        As2[lk + 0][lm] = pack2(av.x, av.x);
        As2[lk + 1][lm] = pack2(av.y, av.y);
        As2[lk + 2][lm] = pack2(av.z, av.z);
        As2[lk + 3][lm] = pack2(av.w, av.w);
        Bs[lk + 0][lm] = bv.x; Bs[lk + 1][lm] = bv.y;
        Bs[lk + 2][lm] = bv.z; Bs[lk + 3][lm] = bv.w;
        __syncthreads();
#pragma unroll
        for (int kk = 0; kk < 16; kk++) {
            ulonglong2 aa0 = *(const ulonglong2*)&As2[kk][ty * 4];
            ulonglong2 aa1 = *(const ulonglong2*)&As2[kk][ty * 4 + 2];
            float4 bvec = *(const float4*)&Bs[kk][tx * 4];
            ull b0 = pack2(bvec.x, bvec.y);
            ull b1 = pack2(bvec.z, bvec.w);
            fma2(acc[0][0], aa0.x, b0); fma2(acc[0][1], aa0.x, b1);
            fma2(acc[1][0], aa0.y, b0); fma2(acc[1][1], aa0.y, b1);
            fma2(acc[2][0], aa1.x, b0); fma2(acc[2][1], aa1.x, b1);
            fma2(acc[3][0], aa1.y, b0); fma2(acc[3][1], aa1.y, b1);
        }
    }
#pragma unroll
    for (int i = 0; i < 4; i++) {
        int m = ty * 4 + i;
        int n = nt * 64 + tx * 4;
        float2 lo = unpack2(acc[i][0]);
        float2 hi = unpack2(acc[i][1]);
        float4 v = make_float4(lo.x, lo.y, hi.x, hi.y);
        *(float4*)&g_partial[((size_t)s * BB + m) * CHN + n] = v;
    }
}

// ---------------------------------------------------------------------------
// Kernel 2 (idx 2): FUSED reduce + stable top-128 + weight gather.
// One block per batch row, 512 threads (one per channel).
// ---------------------------------------------------------------------------
__global__ __launch_bounds__(CHN) void fuse_select(const float* __restrict__ rb,
                                                   const float* __restrict__ cw) {
    __shared__ float sa[CHN];
    __shared__ unsigned char keep[CHN];
    __shared__ int sidx[NKEEP];
    const int m = blockIdx.x;
    const int i = threadIdx.x;

    // reduce split-K partials + bias
    float sum = rb[i];
#pragma unroll 8
    for (int s = 0; s < SPLITK; s++)
        sum += g_partial[((size_t)s * BB + m) * CHN + i];

    // stable top-128 by |score| (jax tie rule: greater, or equal with lower idx)
    float v = fabsf(sum);
    sa[i] = v;
    __syncthreads();
    int rank = 0;
    for (int j = 0; j < CHN; j++) {
        float u = sa[j];
        rank += (u > v) || (u == v && j < i);
    }
    keep[i] = (rank < NKEEP) ? 1 : 0;
    __syncthreads();
    if (keep[i]) {
        int pos = 0;
        for (int j = 0; j < i; j++) pos += keep[j];
        sidx[pos] = i;
        g_idx[m * NKEEP + pos] = i;
    }
    __syncthreads();

    // gather selected weights, K-reordered (tap-major) + tf32 rounding
    for (int t = i; t < NKEEP * 576; t += CHN) {
        int n  = t / 576;
        int kk = t - n * 576;
        int c  = sidx[n];
        g_bw[((size_t)(m * NKEEP + n)) * 576 + kk] =
            to_tf32(cw[(size_t)c * 576 + (kk & 63) * 9 + (kk >> 6)]);
    }
}

// ---------------------------------------------------------------------------
// Kernel 4 (idx 3 -> gets profiled): conv implicit GEMM, tf32 m16n8k8,
// now double-buffered smem + register prefetch, ONE sync per chunk.
// ---------------------------------------------------------------------------
__global__ __launch_bounds__(256) void conv_mma(const float* __restrict__ cb,
                                                float* __restrict__ out) {
    __shared__ __align__(16) float sA[2][8 * 4 * 32 * 4];    // 2 x 16 KB
    __shared__ __align__(16) float sB[2][16 * 4 * 32 * 2];   // 2 x 16 KB
    __shared__ float sbias[NKEEP];

    const int tid  = threadIdx.x;
    const int lane = tid & 31;
    const int wid  = tid >> 5;
    const int wm   = wid & 1;
    const int wn   = wid >> 1;
    const int t = blockIdx.x;
    const int b = blockIdx.y;

    if (tid < NKEEP) sbias[tid] = cb[g_idx[b * NKEEP + tid]];

    const int m_row = tid >> 1;
    const int ks    = (tid & 1) * 16;
    const int s  = t * 128 + m_row;
    const int hh = s / WW;
    const int ww = s % WW;
    const float* bsrc = g_bw + ((size_t)(b * NKEEP + m_row)) * 576 + ks;
    const float* abase = g_xt + (((size_t)b * SPAT) << 6) + (ks & 31);

    const int a_mt  = m_row >> 4;
    const int a_row = m_row & 15;
    const int a_laneb = (a_row & 7) << 2;
    const int a_slotb = a_row >> 3;
    const int b_nt  = m_row >> 3;
    const int b_nin = m_row & 7;

    float acc[4][4][4];
#pragma unroll
    for (int mt = 0; mt < 4; mt++)
#pragma unroll
        for (int nt = 0; nt < 4; nt++)
#pragma unroll
            for (int r = 0; r < 4; r++) acc[mt][nt][r] = 0.f;

    // ---- helpers as lambdas ----
    auto load_chunk = [&](int kc, float* av, float* bv) {
        const int tap = kc >> 1;
        const int hc  = kc & 1;
        const int hp = hh + tap / 3 - 1;
        const int wp = ww + tap % 3 - 1;
        const bool valid = (s < SPAT) && ((unsigned)hp < (unsigned)HH) &&
                           ((unsigned)wp < (unsigned)WW);
        if (valid) {
            const float* asrc = abase + (((size_t)(hp * WW + wp)) << 6) + hc * 32;
#pragma unroll
            for (int i = 0; i < 4; i++) *(float4*)&av[i * 4] = *(const float4*)(asrc + i * 4);
        } else {
#pragma unroll
            for (int i = 0; i < 16; i++) av[i] = 0.f;
        }
#pragma unroll
        for (int i = 0; i < 4; i++) *(float4*)&bv[i * 4] = *(const float4*)(bsrc + kc * 32 + i * 4);
    };
    auto scatter_chunk = [&](int p, const float* av, const float* bv) {
#pragma unroll
        for (int i = 0; i < 16; i++) {
            int k  = ks + i;
            int k8 = k >> 3, col = k & 7;
            int lanei = a_laneb | (col & 3);
            int sloti = a_slotb | ((col >> 2) << 1);
            sA[p][((((a_mt << 2) | k8) << 5) | lanei) * 4 + sloti] = av[i];
        }
#pragma unroll
        for (int i = 0; i < 16; i++) {
            int k  = ks + i;
            int k8 = k >> 3, kin = k & 7;
            int lanei = (b_nin << 2) | (kin & 3);
            int sloti = kin >> 2;
            sB[p][((((b_nt << 2) | k8) << 5) | lanei) * 2 + sloti] = bv[i];
        }
    };
    auto compute_chunk = [&](int p) {
#pragma unroll
        for (int k8 = 0; k8 < 4; k8++) {
            uint32_t af[4][4];
#pragma unroll
            for (int mt = 0; mt < 4; mt++) {
                float4 v = *(const float4*)&sA[p][((((wm * 4 + mt) << 2) | k8) << 5 | lane) * 4];
                af[mt][0] = __float_as_uint(v.x); af[mt][1] = __float_as_uint(v.y);
                af[mt][2] = __float_as_uint(v.z); af[mt][3] = __float_as_uint(v.w);
            }
            uint32_t bf[4][2];
#pragma unroll
            for (int nt = 0; nt < 4; nt++) {
                float2 v = *(const float2*)&sB[p][((((wn * 4 + nt) << 2) | k8) << 5 | lane) * 2];
                bf[nt][0] = __float_as_uint(v.x); bf[nt][1] = __float_as_uint(v.y);
            }
#pragma unroll
            for (int mt = 0; mt < 4; mt++)
#pragma unroll
                for (int nt = 0; nt < 4; nt++)
                    mma_tf32(acc[mt][nt], af[mt], bf[nt]);
        }
    };

    // ---- software-pipelined mainloop: 1 sync/chunk, LDG overlapped w/ MMA ----
    float avA[16], bvA[16], avB[16], bvB[16];
    load_chunk(0, avA, bvA);
#pragma unroll 1
    for (int kc2 = 0; kc2 < KCHUNKS; kc2 += 2) {
        // even chunk -> buffer 0
        scatter_chunk(0, avA, bvA);
        __syncthreads();
        load_chunk(kc2 + 1, avB, bvB);            // prefetch next (always < 18)
        compute_chunk(0);
        // odd chunk -> buffer 1
        scatter_chunk(1, avB, bvB);
        __syncthreads();
        if (kc2 + 2 < KCHUNKS) load_chunk(kc2 + 2, avA, bvA);
        compute_chunk(1);
    }

    // epilogue: bias + store
    const int row0 = lane >> 2;
    const int col0 = (lane & 3) * 2;
#pragma unroll
    for (int mt = 0; mt < 4; mt++) {
#pragma unroll
        for (int nt = 0; nt < 4; nt++) {
            int n  = wn * 32 + nt * 8 + col0;
            int sr = t * 128 + wm * 64 + mt * 16 + row0;
            float b0 = sbias[n], b1 = sbias[n + 1];
            float* op0 = out + ((size_t)b * NKEEP + n) * SPAT;
            float* op1 = op0 + SPAT;
            if (sr < SPAT) {
                op0[sr] = acc[mt][nt][0] + b0;
                op1[sr] = acc[mt][nt][1] + b1;
            }
            if (sr + 8 < SPAT) {
                op0[sr + 8] = acc[mt][nt][2] + b0;
                op1[sr + 8] = acc[mt][nt][3] + b1;
            }
        }
    }
}

// ---------------------------------------------------------------------------
extern "C" void kernel_launch(void* const* d_in, const int* in_sizes, int n_in,
                              void* d_out, int out_size) {
    const float* x  = (const float*)d_in[0];   // [64,64,56,56]
    const float* cw = (const float*)d_in[1];   // [512,64,3,3]
    const float* cb = (const float*)d_in[2];   // [512]
    const float* rw = (const float*)d_in[3];   // [512,200704]
    const float* rb = (const float*)d_in[4];   // [512]
    float* out = (float*)d_out;                // [64,128,56,56]

    transpose_x<<<dim3(SPAT / 32, CIN / 32, BB), dim3(32, 8)>>>(x);  // idx 0
    router_gemm<<<dim3(8, SPLITK), 256>>>(x, rw);                     // idx 1
    fuse_select<<<BB, CHN>>>(rb, cw);                                 // idx 2
    conv_mma<<<dim3(NTILES, BB), 256>>>(cb, out);                     // idx 3 (profiled)
}

// round 7
// speedup vs baseline: 1.2962x; 1.1820x over previous
#include <cuda_runtime.h>
#include <cstdint>

#define BB    64
#define CIN   64
#define HH    56
#define WW    56
#define CHN   512
#define IN_DIM (CIN*HH*WW)      // 200704
#define NKEEP 128
#define SPLITK 64
#define KC (IN_DIM/SPLITK)      // 3136
#define SPAT (HH*WW)            // 3136
#define NTILES 25               // ceil(3136/128)
#define KCHUNKS 18              // 9 taps * 2 ci-halves of 32
#define ASTRIDE 36              // padded row stride (floats): conflict-free banks

typedef unsigned long long ull;

// ---------------- small helpers ----------------
__device__ __forceinline__ ull pack2(float lo, float hi) {
    ull r; asm("mov.b64 %0, {%1,%2};" : "=l"(r) : "f"(lo), "f"(hi)); return r;
}
__device__ __forceinline__ float2 unpack2(ull v) {
    float2 f; asm("mov.b64 {%0,%1}, %2;" : "=f"(f.x), "=f"(f.y) : "l"(v)); return f;
}
__device__ __forceinline__ void fma2(ull& d, ull a, ull b) {
    asm("fma.rn.f32x2 %0, %1, %2, %0;" : "+l"(d) : "l"(a), "l"(b));
}
__device__ __forceinline__ float to_tf32(float f) {
    uint32_t u; asm("cvt.rna.tf32.f32 %0, %1;" : "=r"(u) : "f"(f));
    return __uint_as_float(u);
}
__device__ __forceinline__ void mma_tf32(float* c, const uint32_t* a, const uint32_t* b) {
    asm volatile(
        "mma.sync.aligned.m16n8k8.row.col.f32.tf32.tf32.f32 "
        "{%0,%1,%2,%3}, {%4,%5,%6,%7}, {%8,%9}, {%0,%1,%2,%3};"
        : "+f"(c[0]), "+f"(c[1]), "+f"(c[2]), "+f"(c[3])
        : "r"(a[0]), "r"(a[1]), "r"(a[2]), "r"(a[3]), "r"(b[0]), "r"(b[1]));
}
__device__ __forceinline__ void cp16(uint32_t dst_smem, const void* src, uint32_t srcsz) {
    asm volatile("cp.async.cg.shared.global [%0], [%1], 16, %2;"
                 :: "r"(dst_smem), "l"(src), "r"(srcsz));
}
#define CP_COMMIT() asm volatile("cp.async.commit_group;" ::: "memory")
#define CP_WAIT0()  asm volatile("cp.async.wait_group 0;" ::: "memory")

// ---------------- scratch ----------------
__device__ float g_partial[SPLITK * BB * CHN];  // 8 MB
__device__ int   g_idx[BB * NKEEP];
__device__ float g_xt[(size_t)BB * SPAT * CIN];   // x channels-last, tf32-rounded
__device__ float g_bw[(size_t)BB * NKEEP * 576];  // gathered weights [b][n][tap*64+ci]

// ---------------------------------------------------------------------------
// Kernel T (idx 0): transpose x to channels-last, rounding to tf32.
// ---------------------------------------------------------------------------
__global__ __launch_bounds__(256) void transpose_x(const float* __restrict__ x) {
    __shared__ float tile[32][33];
    const int s0 = blockIdx.x * 32;
    const int c0 = blockIdx.y * 32;
    const int b  = blockIdx.z;
    const int tx = threadIdx.x;
    const int ty = threadIdx.y;
#pragma unroll
    for (int k = 0; k < 4; k++) {
        int ci = c0 + ty + k * 8;
        tile[ty + k * 8][tx] = x[((size_t)b * CIN + ci) * SPAT + s0 + tx];
    }
    __syncthreads();
#pragma unroll
    for (int k = 0; k < 4; k++) {
        int srow = s0 + ty + k * 8;
        g_xt[((size_t)b * SPAT + srow) * CIN + c0 + tx] = to_tf32(tile[tx][ty + k * 8]);
    }
}

// ---------------------------------------------------------------------------
// Kernel 1 (idx 1): router GEMM partials via packed f32x2 FMA (proven).
// ---------------------------------------------------------------------------
__global__ __launch_bounds__(256) void router_gemm(const float* __restrict__ x,
                                                   const float* __restrict__ rw) {
    const int nt = blockIdx.x;
    const int s  = blockIdx.y;
    __shared__ __align__(16) ull   As2[16][64];
    __shared__ __align__(16) float Bs[16][68];

    const int tid = threadIdx.x;
    const int tx = tid & 15;
    const int ty = tid >> 4;
    const int lm = tid >> 2;
    const int lk = (tid & 3) * 4;

    const float* xp = x  + (size_t)lm * IN_DIM + (size_t)s * KC;
    const float* wp = rw + (size_t)(nt * 64 + lm) * IN_DIM + (size_t)s * KC;

    ull acc[4][2];
#pragma unroll
    for (int i = 0; i < 4; i++) { acc[i][0] = 0ull; acc[i][1] = 0ull; }

    for (int k0 = 0; k0 < KC; k0 += 16) {
        float4 av = *(const float4*)(xp + k0 + lk);
        float4 bv = *(const float4*)(wp + k0 + lk);
        __syncthreads();
        As2[lk + 0][lm] = pack2(av.x, av.x);
        As2[lk + 1][lm] = pack2(av.y, av.y);
        As2[lk + 2][lm] = pack2(av.z, av.z);
        As2[lk + 3][lm] = pack2(av.w, av.w);
        Bs[lk + 0][lm] = bv.x; Bs[lk + 1][lm] = bv.y;
        Bs[lk + 2][lm] = bv.z; Bs[lk + 3][lm] = bv.w;
        __syncthreads();
#pragma unroll
        for (int kk = 0; kk < 16; kk++) {
            ulonglong2 aa0 = *(const ulonglong2*)&As2[kk][ty * 4];
            ulonglong2 aa1 = *(const ulonglong2*)&As2[kk][ty * 4 + 2];
            float4 bvec = *(const float4*)&Bs[kk][tx * 4];
            ull b0 = pack2(bvec.x, bvec.y);
            ull b1 = pack2(bvec.z, bvec.w);
            fma2(acc[0][0], aa0.x, b0); fma2(acc[0][1], aa0.x, b1);
            fma2(acc[1][0], aa0.y, b0); fma2(acc[1][1], aa0.y, b1);
            fma2(acc[2][0], aa1.x, b0); fma2(acc[2][1], aa1.x, b1);
            fma2(acc[3][0], aa1.y, b0); fma2(acc[3][1], aa1.y, b1);
        }
    }
#pragma unroll
    for (int i = 0; i < 4; i++) {
        int m = ty * 4 + i;
        int n = nt * 64 + tx * 4;
        float2 lo = unpack2(acc[i][0]);
        float2 hi = unpack2(acc[i][1]);
        float4 v = make_float4(lo.x, lo.y, hi.x, hi.y);
        *(float4*)&g_partial[((size_t)s * BB + m) * CHN + n] = v;
    }
}

// ---------------------------------------------------------------------------
// Kernel 2 (idx 2): FUSED reduce + stable top-128 + weight gather.
// ---------------------------------------------------------------------------
__global__ __launch_bounds__(CHN) void fuse_select(const float* __restrict__ rb,
                                                   const float* __restrict__ cw) {
    __shared__ float sa[CHN];
    __shared__ unsigned char keep[CHN];
    __shared__ int sidx[NKEEP];
    const int m = blockIdx.x;
    const int i = threadIdx.x;

    float sum = rb[i];
#pragma unroll 8
    for (int s = 0; s < SPLITK; s++)
        sum += g_partial[((size_t)s * BB + m) * CHN + i];

    float v = fabsf(sum);
    sa[i] = v;
    __syncthreads();
    int rank = 0;
    for (int j = 0; j < CHN; j++) {
        float u = sa[j];
        rank += (u > v) || (u == v && j < i);
    }
    keep[i] = (rank < NKEEP) ? 1 : 0;
    __syncthreads();
    if (keep[i]) {
        int pos = 0;
        for (int j = 0; j < i; j++) pos += keep[j];
        sidx[pos] = i;
        g_idx[m * NKEEP + pos] = i;
    }
    __syncthreads();

    for (int t = i; t < NKEEP * 576; t += CHN) {
        int n  = t / 576;
        int kk = t - n * 576;
        int c  = sidx[n];
        g_bw[((size_t)(m * NKEEP + n)) * 576 + kk] =
            to_tf32(cw[(size_t)c * 576 + (kk & 63) * 9 + (kk >> 6)]);
    }
}

// ---------------------------------------------------------------------------
// Kernel 4 (idx 3, profiled): conv implicit GEMM, tf32 m16n8k8.
// cp.async 2-stage pipeline into NATURAL padded smem (stride 36 floats);
// fragments built by conflict-free scalar LDS. No STS, no reg staging.
// ---------------------------------------------------------------------------
__global__ __launch_bounds__(256, 2) void conv_mma(const float* __restrict__ cb,
                                                   float* __restrict__ out) {
    extern __shared__ float dyn[];
    // per stage: A 128 rows x 36, then B 128 rows x 36  (9216 floats = 36 KB)
    __shared__ float sbias[NKEEP];

    const int tid  = threadIdx.x;
    const int lane = tid & 31;
    const int wid  = tid >> 5;
    const int wm   = wid & 1;     // m half (64 rows)
    const int wn   = wid >> 1;    // n quarter (32 cols)
    const int t = blockIdx.x;
    const int b = blockIdx.y;

    if (tid < NKEEP) sbias[tid] = cb[g_idx[b * NKEEP + tid]];

    // staging role: row r (0..127), half (0/1) of the 32-float k-chunk
    const int r    = tid >> 1;
    const int half = tid & 1;
    const int s_st = t * 128 + r;
    const int hh = s_st / WW;
    const int ww = s_st % WW;
    const float* bsrc0 = g_bw + ((size_t)(b * NKEEP + r)) * 576 + half * 16;
    const float* abase = g_xt + (((size_t)b * SPAT) << 6) + half * 16;

    uint32_t smem_base = (uint32_t)__cvta_generic_to_shared(dyn);
    // byte offsets of this thread's staging destinations
    const uint32_t dstA0 = smem_base + (r * ASTRIDE + half * 16) * 4;
    const uint32_t dstB0 = smem_base + (128 * ASTRIDE + r * ASTRIDE + half * 16) * 4;
    const uint32_t stageB = 2 * 128 * ASTRIDE * 4;   // bytes per stage

    auto issue_chunk = [&](int kc, int p) {
        const int tap = kc >> 1;
        const int hc  = kc & 1;
        const int hp = hh + tap / 3 - 1;
        const int wp = ww + tap % 3 - 1;
        const bool valid = (s_st < SPAT) && ((unsigned)hp < (unsigned)HH) &&
                           ((unsigned)wp < (unsigned)WW);
        const uint32_t sz = valid ? 16u : 0u;
        int off = valid ? (hp * WW + wp) : 0;
        const float* asrc = abase + (((size_t)off) << 6) + hc * 32;
        const float* bsrc = bsrc0 + kc * 32;
        const uint32_t dA = dstA0 + p * stageB;
        const uint32_t dB = dstB0 + p * stageB;
#pragma unroll
        for (int j = 0; j < 4; j++) cp16(dA + j * 16, asrc + j * 4, sz);
#pragma unroll
        for (int j = 0; j < 4; j++) cp16(dB + j * 16, bsrc + j * 4, 16u);
        CP_COMMIT();
    };

    float acc[4][4][4];
#pragma unroll
    for (int mt = 0; mt < 4; mt++)
#pragma unroll
        for (int nt = 0; nt < 4; nt++)
#pragma unroll
            for (int q = 0; q < 4; q++) acc[mt][nt][q] = 0.f;

    // fragment base indices (floats) within a stage
    const int lr = lane >> 2;      // 0..7
    const int lc = lane & 3;       // 0..3
    const float* sAf = dyn;
    const float* sBf = dyn + 128 * ASTRIDE;
    const int aRow0 = wm * 64 + lr;           // + mt*16 (+8)
    const int bRow0 = wn * 32 + lr;           // + nt*8

    issue_chunk(0, 0);

#pragma unroll 1
    for (int kc = 0; kc < KCHUNKS; kc++) {
        const int p = kc & 1;
        CP_WAIT0();
        __syncthreads();
        if (kc + 1 < KCHUNKS) issue_chunk(kc + 1, p ^ 1);

        const float* A = sAf + p * 2 * 128 * ASTRIDE;
        const float* B = sBf + p * 2 * 128 * ASTRIDE;
#pragma unroll
        for (int k8 = 0; k8 < 4; k8++) {
            const int k0 = k8 * 8 + lc;
            uint32_t af[4][4];
#pragma unroll
            for (int mt = 0; mt < 4; mt++) {
                const float* ap = A + (aRow0 + mt * 16) * ASTRIDE + k0;
                af[mt][0] = __float_as_uint(ap[0]);
                af[mt][1] = __float_as_uint(ap[8 * ASTRIDE]);
                af[mt][2] = __float_as_uint(ap[4]);
                af[mt][3] = __float_as_uint(ap[8 * ASTRIDE + 4]);
            }
            uint32_t bf[4][2];
#pragma unroll
            for (int nt = 0; nt < 4; nt++) {
                const float* bp = B + (bRow0 + nt * 8) * ASTRIDE + k0;
                bf[nt][0] = __float_as_uint(bp[0]);
                bf[nt][1] = __float_as_uint(bp[4]);
            }
#pragma unroll
            for (int mt = 0; mt < 4; mt++)
#pragma unroll
                for (int nt = 0; nt < 4; nt++)
                    mma_tf32(acc[mt][nt], af[mt], bf[nt]);
        }
    }

    // epilogue: bias + store. c0:(r,c) c1:(r,c+1) c2:(r+8,c) c3:(r+8,c+1)
    const int row0 = lane >> 2;
    const int col0 = (lane & 3) * 2;
#pragma unroll
    for (int mt = 0; mt < 4; mt++) {
#pragma unroll
        for (int nt = 0; nt < 4; nt++) {
            int n  = wn * 32 + nt * 8 + col0;
            int sr = t * 128 + wm * 64 + mt * 16 + row0;
            float b0 = sbias[n], b1 = sbias[n + 1];
            float* op0 = out + ((size_t)b * NKEEP + n) * SPAT;
            float* op1 = op0 + SPAT;
            if (sr < SPAT) {
                op0[sr] = acc[mt][nt][0] + b0;
                op1[sr] = acc[mt][nt][1] + b1;
            }
            if (sr + 8 < SPAT) {
                op0[sr + 8] = acc[mt][nt][2] + b0;
                op1[sr + 8] = acc[mt][nt][3] + b1;
            }
        }
    }
}

// ---------------------------------------------------------------------------
extern "C" void kernel_launch(void* const* d_in, const int* in_sizes, int n_in,
                              void* d_out, int out_size) {
    const float* x  = (const float*)d_in[0];   // [64,64,56,56]
    const float* cw = (const float*)d_in[1];   // [512,64,3,3]
    const float* cb = (const float*)d_in[2];   // [512]
    const float* rw = (const float*)d_in[3];   // [512,200704]
    const float* rb = (const float*)d_in[4];   // [512]
    float* out = (float*)d_out;                // [64,128,56,56]

    const int dynsmem = 2 * 2 * 128 * ASTRIDE * 4;   // 73728 bytes
    cudaFuncSetAttribute(conv_mma, cudaFuncAttributeMaxDynamicSharedMemorySize, dynsmem);

    transpose_x<<<dim3(SPAT / 32, CIN / 32, BB), dim3(32, 8)>>>(x);  // idx 0
    router_gemm<<<dim3(8, SPLITK), 256>>>(x, rw);                     // idx 1
    fuse_select<<<BB, CHN>>>(rb, cw);                                 // idx 2
    conv_mma<<<dim3(NTILES, BB), 256, dynsmem>>>(cb, out);            // idx 3 (profiled)
}

// round 8
// speedup vs baseline: 2.0363x; 1.5709x over previous
#include <cuda_runtime.h>
#include <cstdint>

#define BB    64
#define CIN   64
#define HH    56
#define WW    56
#define CHN   512
#define IN_DIM (CIN*HH*WW)      // 200704
#define NKEEP 128
#define SPLITK 64
#define KC (IN_DIM/SPLITK)      // 3136
#define SPAT (HH*WW)            // 3136
#define NTILES 25               // ceil(3136/128)
#define KCHUNKS 18              // 9 taps * 2 ci-halves of 32
#define ASTRIDE 36              // padded row stride (floats): conflict-free banks
#define RKCH (KC/32)            // 98 router k-chunks per split

// ---------------- small helpers ----------------
__device__ __forceinline__ float to_tf32(float f) {
    uint32_t u; asm("cvt.rna.tf32.f32 %0, %1;" : "=r"(u) : "f"(f));
    return __uint_as_float(u);
}
__device__ __forceinline__ void mma_tf32(float* c, const uint32_t* a, const uint32_t* b) {
    asm volatile(
        "mma.sync.aligned.m16n8k8.row.col.f32.tf32.tf32.f32 "
        "{%0,%1,%2,%3}, {%4,%5,%6,%7}, {%8,%9}, {%0,%1,%2,%3};"
        : "+f"(c[0]), "+f"(c[1]), "+f"(c[2]), "+f"(c[3])
        : "r"(a[0]), "r"(a[1]), "r"(a[2]), "r"(a[3]), "r"(b[0]), "r"(b[1]));
}
__device__ __forceinline__ void cp16(uint32_t dst_smem, const void* src, uint32_t srcsz) {
    asm volatile("cp.async.cg.shared.global [%0], [%1], 16, %2;"
                 :: "r"(dst_smem), "l"(src), "r"(srcsz));
}
#define CP_COMMIT() asm volatile("cp.async.commit_group;" ::: "memory")
#define CP_WAIT0()  asm volatile("cp.async.wait_group 0;" ::: "memory")

// exact hi/lo split: hi is exactly tf32-representable, lo = v - hi exactly.
__device__ __forceinline__ void split_tf32(float v, uint32_t& hi, uint32_t& lo) {
    uint32_t u = __float_as_uint(v) & 0xFFFFE000u;
    hi = u;
    lo = __float_as_uint(v - __uint_as_float(u));
}

// ---------------- scratch ----------------
__device__ float g_partial[SPLITK * BB * CHN];  // 8 MB
__device__ int   g_idx[BB * NKEEP];
__device__ float g_xt[(size_t)BB * SPAT * CIN];   // x channels-last, tf32-rounded
__device__ float g_bw[(size_t)BB * NKEEP * 576];  // gathered weights [b][n][tap*64+ci]

// ---------------------------------------------------------------------------
// Kernel T (idx 0): transpose x to channels-last, rounding to tf32.
// ---------------------------------------------------------------------------
__global__ __launch_bounds__(256) void transpose_x(const float* __restrict__ x) {
    __shared__ float tile[32][33];
    const int s0 = blockIdx.x * 32;
    const int c0 = blockIdx.y * 32;
    const int b  = blockIdx.z;
    const int tx = threadIdx.x;
    const int ty = threadIdx.y;
#pragma unroll
    for (int k = 0; k < 4; k++) {
        int ci = c0 + ty + k * 8;
        tile[ty + k * 8][tx] = x[((size_t)b * CIN + ci) * SPAT + s0 + tx];
    }
    __syncthreads();
#pragma unroll
    for (int k = 0; k < 4; k++) {
        int srow = s0 + ty + k * 8;
        g_xt[((size_t)b * SPAT + srow) * CIN + c0 + tx] = to_tf32(tile[tx][ty + k * 8]);
    }
}

// ---------------------------------------------------------------------------
// Kernel 1 (idx 1): router GEMM partials on tensor cores, tf32x3 (masked
// hi/lo split in registers). scores[m,n] = sum_k x[m,k]*rw[n,k].
// Grid (8 n-tiles, 64 k-splits); 256 thr = 8 warps (2m x 4n);
// tile M=64 x N=64. cp.async 2-stage pipeline, natural padded smem,
// conflict-free scalar-LDS fragments, one sync per 32-K chunk.
// ---------------------------------------------------------------------------
__global__ __launch_bounds__(256) void router_tc(const float* __restrict__ x,
                                                 const float* __restrict__ rw) {
    __shared__ __align__(16) float sA[2][64 * ASTRIDE];   // 2 x 9 KB
    __shared__ __align__(16) float sB[2][64 * ASTRIDE];   // 2 x 9 KB

    const int ntile = blockIdx.x;    // 0..7
    const int sk    = blockIdx.y;    // 0..63
    const int tid  = threadIdx.x;
    const int lane = tid & 31;
    const int wid  = tid >> 5;
    const int wm   = wid & 1;        // m half (32 rows)
    const int wn   = wid >> 1;       // n quarter (16 cols)

    // staging: row r = tid>>2 (0..63), quarter q = tid&3 -> 8 floats at q*8
    const int r = tid >> 2;
    const int q = tid & 3;
    const float* asrc0 = x  + (size_t)r * IN_DIM + (size_t)sk * KC + q * 8;
    const float* bsrc0 = rw + (size_t)(ntile * 64 + r) * IN_DIM + (size_t)sk * KC + q * 8;
    const uint32_t dstA = (uint32_t)__cvta_generic_to_shared(&sA[0][r * ASTRIDE + q * 8]);
    const uint32_t dstB = (uint32_t)__cvta_generic_to_shared(&sB[0][r * ASTRIDE + q * 8]);
    const uint32_t stageBytes = sizeof(float) * 64 * ASTRIDE;

    auto issue = [&](int kc, int p) {
        const int k0 = kc * 32;
        cp16(dstA + p * stageBytes,      asrc0 + k0,     16u);
        cp16(dstA + p * stageBytes + 16, asrc0 + k0 + 4, 16u);
        cp16(dstB + p * stageBytes,      bsrc0 + k0,     16u);
        cp16(dstB + p * stageBytes + 16, bsrc0 + k0 + 4, 16u);
        CP_COMMIT();
    };

    float acc[2][2][4];
#pragma unroll
    for (int mt = 0; mt < 2; mt++)
#pragma unroll
        for (int nt = 0; nt < 2; nt++)
#pragma unroll
            for (int c = 0; c < 4; c++) acc[mt][nt][c] = 0.f;

    const int lr = lane >> 2;
    const int lc = lane & 3;
    const int aRow0 = wm * 32 + lr;
    const int bRow0 = wn * 16 + lr;

    issue(0, 0);

#pragma unroll 1
    for (int kc = 0; kc < RKCH; kc++) {
        const int p = kc & 1;
        CP_WAIT0();
        __syncthreads();
        if (kc + 1 < RKCH) issue(kc + 1, p ^ 1);

        const float* A = sA[p];
        const float* B = sB[p];
#pragma unroll
        for (int k8 = 0; k8 < 4; k8++) {
            const int k0 = k8 * 8 + lc;
            uint32_t ah[2][4], al[2][4];
#pragma unroll
            for (int mt = 0; mt < 2; mt++) {
                const float* ap = A + (aRow0 + mt * 16) * ASTRIDE + k0;
                split_tf32(ap[0],               ah[mt][0], al[mt][0]);
                split_tf32(ap[8 * ASTRIDE],     ah[mt][1], al[mt][1]);
                split_tf32(ap[4],               ah[mt][2], al[mt][2]);
                split_tf32(ap[8 * ASTRIDE + 4], ah[mt][3], al[mt][3]);
            }
            uint32_t bh[2][2], bl[2][2];
#pragma unroll
            for (int nt = 0; nt < 2; nt++) {
                const float* bp = B + (bRow0 + nt * 8) * ASTRIDE + k0;
                split_tf32(bp[0], bh[nt][0], bl[nt][0]);
                split_tf32(bp[4], bh[nt][1], bl[nt][1]);
            }
#pragma unroll
            for (int mt = 0; mt < 2; mt++)
#pragma unroll
                for (int nt = 0; nt < 2; nt++) {
                    mma_tf32(acc[mt][nt], al[mt], bh[nt]);
                    mma_tf32(acc[mt][nt], ah[mt], bl[nt]);
                    mma_tf32(acc[mt][nt], ah[mt], bh[nt]);
                }
        }
    }

    // store partials: c0:(r,c) c1:(r,c+1) c2:(r+8,c) c3:(r+8,c+1)
    const int row0 = lane >> 2;
    const int col0 = (lane & 3) * 2;
#pragma unroll
    for (int mt = 0; mt < 2; mt++) {
#pragma unroll
        for (int nt = 0; nt < 2; nt++) {
            int m = wm * 32 + mt * 16 + row0;
            int n = ntile * 64 + wn * 16 + nt * 8 + col0;
            float* p0 = &g_partial[((size_t)sk * BB + m) * CHN + n];
            p0[0] = acc[mt][nt][0];
            p0[1] = acc[mt][nt][1];
            float* p1 = p0 + 8 * CHN;
            p1[0] = acc[mt][nt][2];
            p1[1] = acc[mt][nt][3];
        }
    }
}

// ---------------------------------------------------------------------------
// Kernel 2 (idx 2): FUSED reduce + stable top-128 + weight gather.
// ---------------------------------------------------------------------------
__global__ __launch_bounds__(CHN) void fuse_select(const float* __restrict__ rb,
                                                   const float* __restrict__ cw) {
    __shared__ float sa[CHN];
    __shared__ unsigned char keep[CHN];
    __shared__ int sidx[NKEEP];
    const int m = blockIdx.x;
    const int i = threadIdx.x;

    float sum = rb[i];
#pragma unroll 8
    for (int s = 0; s < SPLITK; s++)
        sum += g_partial[((size_t)s * BB + m) * CHN + i];

    float v = fabsf(sum);
    sa[i] = v;
    __syncthreads();
    int rank = 0;
    for (int j = 0; j < CHN; j++) {
        float u = sa[j];
        rank += (u > v) || (u == v && j < i);
    }
    keep[i] = (rank < NKEEP) ? 1 : 0;
    __syncthreads();
    if (keep[i]) {
        int pos = 0;
        for (int j = 0; j < i; j++) pos += keep[j];
        sidx[pos] = i;
        g_idx[m * NKEEP + pos] = i;
    }
    __syncthreads();

    for (int t = i; t < NKEEP * 576; t += CHN) {
        int n  = t / 576;
        int kk = t - n * 576;
        int c  = sidx[n];
        g_bw[((size_t)(m * NKEEP + n)) * 576 + kk] =
            to_tf32(cw[(size_t)c * 576 + (kk & 63) * 9 + (kk >> 6)]);
    }
}

// ---------------------------------------------------------------------------
// Kernel 4 (idx 3, profiled): conv implicit GEMM, tf32 m16n8k8 (proven R7).
// ---------------------------------------------------------------------------
__global__ __launch_bounds__(256, 2) void conv_mma(const float* __restrict__ cb,
                                                   float* __restrict__ out) {
    extern __shared__ float dyn[];
    __shared__ float sbias[NKEEP];

    const int tid  = threadIdx.x;
    const int lane = tid & 31;
    const int wid  = tid >> 5;
    const int wm   = wid & 1;
    const int wn   = wid >> 1;
    const int t = blockIdx.x;
    const int b = blockIdx.y;

    if (tid < NKEEP) sbias[tid] = cb[g_idx[b * NKEEP + tid]];

    const int r    = tid >> 1;
    const int half = tid & 1;
    const int s_st = t * 128 + r;
    const int hh = s_st / WW;
    const int ww = s_st % WW;
    const float* bsrc0 = g_bw + ((size_t)(b * NKEEP + r)) * 576 + half * 16;
    const float* abase = g_xt + (((size_t)b * SPAT) << 6) + half * 16;

    uint32_t smem_base = (uint32_t)__cvta_generic_to_shared(dyn);
    const uint32_t dstA0 = smem_base + (r * ASTRIDE + half * 16) * 4;
    const uint32_t dstB0 = smem_base + (128 * ASTRIDE + r * ASTRIDE + half * 16) * 4;
    const uint32_t stageB = 2 * 128 * ASTRIDE * 4;

    auto issue_chunk = [&](int kc, int p) {
        const int tap = kc >> 1;
        const int hc  = kc & 1;
        const int hp = hh + tap / 3 - 1;
        const int wp = ww + tap % 3 - 1;
        const bool valid = (s_st < SPAT) && ((unsigned)hp < (unsigned)HH) &&
                           ((unsigned)wp < (unsigned)WW);
        const uint32_t sz = valid ? 16u : 0u;
        int off = valid ? (hp * WW + wp) : 0;
        const float* asrc = abase + (((size_t)off) << 6) + hc * 32;
        const float* bsrc = bsrc0 + kc * 32;
        const uint32_t dA = dstA0 + p * stageB;
        const uint32_t dB = dstB0 + p * stageB;
#pragma unroll
        for (int j = 0; j < 4; j++) cp16(dA + j * 16, asrc + j * 4, sz);
#pragma unroll
        for (int j = 0; j < 4; j++) cp16(dB + j * 16, bsrc + j * 4, 16u);
        CP_COMMIT();
    };

    float acc[4][4][4];
#pragma unroll
    for (int mt = 0; mt < 4; mt++)
#pragma unroll
        for (int nt = 0; nt < 4; nt++)
#pragma unroll
            for (int c = 0; c < 4; c++) acc[mt][nt][c] = 0.f;

    const int lr = lane >> 2;
    const int lc = lane & 3;
    const float* sAf = dyn;
    const float* sBf = dyn + 128 * ASTRIDE;
    const int aRow0 = wm * 64 + lr;
    const int bRow0 = wn * 32 + lr;

    issue_chunk(0, 0);

#pragma unroll 1
    for (int kc = 0; kc < KCHUNKS; kc++) {
        const int p = kc & 1;
        CP_WAIT0();
        __syncthreads();
        if (kc + 1 < KCHUNKS) issue_chunk(kc + 1, p ^ 1);

        const float* A = sAf + p * 2 * 128 * ASTRIDE;
        const float* B = sBf + p * 2 * 128 * ASTRIDE;
#pragma unroll
        for (int k8 = 0; k8 < 4; k8++) {
            const int k0 = k8 * 8 + lc;
            uint32_t af[4][4];
#pragma unroll
            for (int mt = 0; mt < 4; mt++) {
                const float* ap = A + (aRow0 + mt * 16) * ASTRIDE + k0;
                af[mt][0] = __float_as_uint(ap[0]);
                af[mt][1] = __float_as_uint(ap[8 * ASTRIDE]);
                af[mt][2] = __float_as_uint(ap[4]);
                af[mt][3] = __float_as_uint(ap[8 * ASTRIDE + 4]);
            }
            uint32_t bf[4][2];
#pragma unroll
            for (int nt = 0; nt < 4; nt++) {
                const float* bp = B + (bRow0 + nt * 8) * ASTRIDE + k0;
                bf[nt][0] = __float_as_uint(bp[0]);
                bf[nt][1] = __float_as_uint(bp[4]);
            }
#pragma unroll
            for (int mt = 0; mt < 4; mt++)
#pragma unroll
                for (int nt = 0; nt < 4; nt++)
                    mma_tf32(acc[mt][nt], af[mt], bf[nt]);
        }
    }

    const int row0 = lane >> 2;
    const int col0 = (lane & 3) * 2;
#pragma unroll
    for (int mt = 0; mt < 4; mt++) {
#pragma unroll
        for (int nt = 0; nt < 4; nt++) {
            int n  = wn * 32 + nt * 8 + col0;
            int sr = t * 128 + wm * 64 + mt * 16 + row0;
            float b0 = sbias[n], b1 = sbias[n + 1];
            float* op0 = out + ((size_t)b * NKEEP + n) * SPAT;
            float* op1 = op0 + SPAT;
            if (sr < SPAT) {
                op0[sr] = acc[mt][nt][0] + b0;
                op1[sr] = acc[mt][nt][1] + b1;
            }
            if (sr + 8 < SPAT) {
                op0[sr + 8] = acc[mt][nt][2] + b0;
                op1[sr + 8] = acc[mt][nt][3] + b1;
            }
        }
    }
}

// ---------------------------------------------------------------------------
extern "C" void kernel_launch(void* const* d_in, const int* in_sizes, int n_in,
                              void* d_out, int out_size) {
    const float* x  = (const float*)d_in[0];   // [64,64,56,56]
    const float* cw = (const float*)d_in[1];   // [512,64,3,3]
    const float* cb = (const float*)d_in[2];   // [512]
    const float* rw = (const float*)d_in[3];   // [512,200704]
    const float* rb = (const float*)d_in[4];   // [512]
    float* out = (float*)d_out;                // [64,128,56,56]

    const int dynsmem = 2 * 2 * 128 * ASTRIDE * 4;   // 73728 bytes
    cudaFuncSetAttribute(conv_mma, cudaFuncAttributeMaxDynamicSharedMemorySize, dynsmem);

    transpose_x<<<dim3(SPAT / 32, CIN / 32, BB), dim3(32, 8)>>>(x);  // idx 0
    router_tc<<<dim3(8, SPLITK), 256>>>(x, rw);                       // idx 1
    fuse_select<<<BB, CHN>>>(rb, cw);                                 // idx 2
    conv_mma<<<dim3(NTILES, BB), 256, dynsmem>>>(cb, out);            // idx 3 (profiled)
}

// round 9
// speedup vs baseline: 2.1881x; 1.0746x over previous
#include <cuda_runtime.h>
#include <cstdint>

#define BB    64
#define CIN   64
#define HH    56
#define WW    56
#define CHN   512
#define IN_DIM (CIN*HH*WW)      // 200704
#define NKEEP 128
#define SPLITK 112
#define KC (IN_DIM/SPLITK)      // 1792
#define SPAT (HH*WW)            // 3136
#define NTILES 25               // ceil(3136/128)
#define KCHUNKS 18              // 9 taps * 2 ci-halves of 32
#define ASTRIDE 36              // padded row stride (floats): conflict-free banks
#define RKCH (KC/32)            // 56 router k-chunks per split
#define RSTAGE ((64+128)*ASTRIDE)   // floats per router stage (A 64 rows + B 128 rows)

// ---------------- small helpers ----------------
__device__ __forceinline__ float to_tf32(float f) {
    uint32_t u; asm("cvt.rna.tf32.f32 %0, %1;" : "=r"(u) : "f"(f));
    return __uint_as_float(u);
}
__device__ __forceinline__ void mma_tf32(float* c, const uint32_t* a, const uint32_t* b) {
    asm volatile(
        "mma.sync.aligned.m16n8k8.row.col.f32.tf32.tf32.f32 "
        "{%0,%1,%2,%3}, {%4,%5,%6,%7}, {%8,%9}, {%0,%1,%2,%3};"
        : "+f"(c[0]), "+f"(c[1]), "+f"(c[2]), "+f"(c[3])
        : "r"(a[0]), "r"(a[1]), "r"(a[2]), "r"(a[3]), "r"(b[0]), "r"(b[1]));
}
__device__ __forceinline__ void cp16(uint32_t dst_smem, const void* src, uint32_t srcsz) {
    asm volatile("cp.async.cg.shared.global [%0], [%1], 16, %2;"
                 :: "r"(dst_smem), "l"(src), "r"(srcsz));
}
#define CP_COMMIT() asm volatile("cp.async.commit_group;" ::: "memory")
#define CP_WAIT0()  asm volatile("cp.async.wait_group 0;" ::: "memory")

// exact hi/lo split: hi is exactly tf32-representable, lo = v - hi exactly.
__device__ __forceinline__ void split_tf32(float v, uint32_t& hi, uint32_t& lo) {
    uint32_t u = __float_as_uint(v) & 0xFFFFE000u;
    hi = u;
    lo = __float_as_uint(v - __uint_as_float(u));
}

// ---------------- scratch ----------------
__device__ float g_partial[SPLITK * BB * CHN];  // 14.7 MB
__device__ int   g_idx[BB * NKEEP];
__device__ float g_xt[(size_t)BB * SPAT * CIN];   // x channels-last, tf32-rounded
__device__ float g_bw[(size_t)BB * NKEEP * 576];  // gathered weights [b][n][tap*64+ci]

// ---------------------------------------------------------------------------
// Kernel T (idx 0): transpose x to channels-last, rounding to tf32.
// ---------------------------------------------------------------------------
__global__ __launch_bounds__(256) void transpose_x(const float* __restrict__ x) {
    __shared__ float tile[32][33];
    const int s0 = blockIdx.x * 32;
    const int c0 = blockIdx.y * 32;
    const int b  = blockIdx.z;
    const int tx = threadIdx.x;
    const int ty = threadIdx.y;
#pragma unroll
    for (int k = 0; k < 4; k++) {
        int ci = c0 + ty + k * 8;
        tile[ty + k * 8][tx] = x[((size_t)b * CIN + ci) * SPAT + s0 + tx];
    }
    __syncthreads();
#pragma unroll
    for (int k = 0; k < 4; k++) {
        int srow = s0 + ty + k * 8;
        g_xt[((size_t)b * SPAT + srow) * CIN + c0 + tx] = to_tf32(tile[tx][ty + k * 8]);
    }
}

// ---------------------------------------------------------------------------
// Kernel 1 (idx 1): router GEMM partials on tensor cores, tf32x3.
// RETILED: block M=64 (full batch) x N=128; 8 warps (2m x 4n), warp 32x32.
// Per k8 per warp: 16 LDS + 32 split-ALU -> 24 MMAs (was 12 LDS+24 ALU -> 12).
// Grid (CHN/128=4 n-tiles, SPLITK=112 k-splits). cp.async 2-stage pipeline.
// ---------------------------------------------------------------------------
__global__ __launch_bounds__(256) void router_tc(const float* __restrict__ x,
                                                 const float* __restrict__ rw) {
    extern __shared__ float rs[];   // [2][RSTAGE]: A 64x36 then B 128x36

    const int ntile = blockIdx.x;    // 0..3
    const int sk    = blockIdx.y;    // 0..111
    const int tid  = threadIdx.x;
    const int lane = tid & 31;
    const int wid  = tid >> 5;
    const int wm   = wid & 1;        // m half (32 rows)
    const int wn   = wid >> 1;       // n quarter (32 cols)

    // staging: A: unit tid -> row tid>>2, 8 floats at (tid&3)*8  (2 cp16)
    //          B: unit tid -> row tid>>1, 16 floats at (tid&1)*16 (4 cp16)
    const int ar = tid >> 2, aq = tid & 3;
    const int br = tid >> 1, bh2 = tid & 1;
    const float* asrc0 = x  + (size_t)ar * IN_DIM + (size_t)sk * KC + aq * 8;
    const float* bsrc0 = rw + (size_t)(ntile * 128 + br) * IN_DIM + (size_t)sk * KC + bh2 * 16;
    const uint32_t base = (uint32_t)__cvta_generic_to_shared(rs);
    const uint32_t dstA = base + (ar * ASTRIDE + aq * 8) * 4;
    const uint32_t dstB = base + (64 * ASTRIDE + br * ASTRIDE + bh2 * 16) * 4;
    const uint32_t stageBytes = RSTAGE * 4;

    auto issue = [&](int kc, int p) {
        const int k0 = kc * 32;
        const uint32_t dA = dstA + p * stageBytes;
        const uint32_t dB = dstB + p * stageBytes;
        cp16(dA,      asrc0 + k0,      16u);
        cp16(dA + 16, asrc0 + k0 + 4,  16u);
#pragma unroll
        for (int j = 0; j < 4; j++) cp16(dB + j * 16, bsrc0 + k0 + j * 4, 16u);
        CP_COMMIT();
    };

    float acc[2][4][4];
#pragma unroll
    for (int mt = 0; mt < 2; mt++)
#pragma unroll
        for (int nt = 0; nt < 4; nt++)
#pragma unroll
            for (int c = 0; c < 4; c++) acc[mt][nt][c] = 0.f;

    const int lr = lane >> 2;
    const int lc = lane & 3;
    const int aRow0 = wm * 32 + lr;
    const int bRow0 = wn * 32 + lr;

    issue(0, 0);

#pragma unroll 1
    for (int kc = 0; kc < RKCH; kc++) {
        const int p = kc & 1;
        CP_WAIT0();
        __syncthreads();
        if (kc + 1 < RKCH) issue(kc + 1, p ^ 1);

        const float* A = rs + p * RSTAGE;
        const float* B = rs + p * RSTAGE + 64 * ASTRIDE;
#pragma unroll
        for (int k8 = 0; k8 < 4; k8++) {
            const int k0 = k8 * 8 + lc;
            uint32_t ah[2][4], al[2][4];
#pragma unroll
            for (int mt = 0; mt < 2; mt++) {
                const float* ap = A + (aRow0 + mt * 16) * ASTRIDE + k0;
                split_tf32(ap[0],               ah[mt][0], al[mt][0]);
                split_tf32(ap[8 * ASTRIDE],     ah[mt][1], al[mt][1]);
                split_tf32(ap[4],               ah[mt][2], al[mt][2]);
                split_tf32(ap[8 * ASTRIDE + 4], ah[mt][3], al[mt][3]);
            }
            uint32_t bh[4][2], bl[4][2];
#pragma unroll
            for (int nt = 0; nt < 4; nt++) {
                const float* bp = B + (bRow0 + nt * 8) * ASTRIDE + k0;
                split_tf32(bp[0], bh[nt][0], bl[nt][0]);
                split_tf32(bp[4], bh[nt][1], bl[nt][1]);
            }
#pragma unroll
            for (int mt = 0; mt < 2; mt++)
#pragma unroll
                for (int nt = 0; nt < 4; nt++) {
                    mma_tf32(acc[mt][nt], al[mt], bh[nt]);
                    mma_tf32(acc[mt][nt], ah[mt], bl[nt]);
                    mma_tf32(acc[mt][nt], ah[mt], bh[nt]);
                }
        }
    }

    // store partials: c0:(r,c) c1:(r,c+1) c2:(r+8,c) c3:(r+8,c+1)
    const int row0 = lane >> 2;
    const int col0 = (lane & 3) * 2;
#pragma unroll
    for (int mt = 0; mt < 2; mt++) {
#pragma unroll
        for (int nt = 0; nt < 4; nt++) {
            int m = wm * 32 + mt * 16 + row0;
            int n = ntile * 128 + wn * 32 + nt * 8 + col0;
            float* p0 = &g_partial[((size_t)sk * BB + m) * CHN + n];
            p0[0] = acc[mt][nt][0];
            p0[1] = acc[mt][nt][1];
            float* p1 = p0 + 8 * CHN;
            p1[0] = acc[mt][nt][2];
            p1[1] = acc[mt][nt][3];
        }
    }
}

// ---------------------------------------------------------------------------
// Kernel 2 (idx 2): FUSED reduce + stable top-128 + weight gather.
// ---------------------------------------------------------------------------
__global__ __launch_bounds__(CHN) void fuse_select(const float* __restrict__ rb,
                                                   const float* __restrict__ cw) {
    __shared__ float sa[CHN];
    __shared__ unsigned char keep[CHN];
    __shared__ int sidx[NKEEP];
    const int m = blockIdx.x;
    const int i = threadIdx.x;

    float sum = rb[i];
#pragma unroll 8
    for (int s = 0; s < SPLITK; s++)
        sum += g_partial[((size_t)s * BB + m) * CHN + i];

    float v = fabsf(sum);
    sa[i] = v;
    __syncthreads();
    int rank = 0;
    for (int j = 0; j < CHN; j++) {
        float u = sa[j];
        rank += (u > v) || (u == v && j < i);
    }
    keep[i] = (rank < NKEEP) ? 1 : 0;
    __syncthreads();
    if (keep[i]) {
        int pos = 0;
        for (int j = 0; j < i; j++) pos += keep[j];
        sidx[pos] = i;
        g_idx[m * NKEEP + pos] = i;
    }
    __syncthreads();

    for (int t = i; t < NKEEP * 576; t += CHN) {
        int n  = t / 576;
        int kk = t - n * 576;
        int c  = sidx[n];
        g_bw[((size_t)(m * NKEEP + n)) * 576 + kk] =
            to_tf32(cw[(size_t)c * 576 + (kk & 63) * 9 + (kk >> 6)]);
    }
}

// ---------------------------------------------------------------------------
// Kernel 4 (idx 3, profiled): conv implicit GEMM, tf32 m16n8k8 (proven R7).
// ---------------------------------------------------------------------------
__global__ __launch_bounds__(256, 2) void conv_mma(const float* __restrict__ cb,
                                                   float* __restrict__ out) {
    extern __shared__ float dyn[];
    __shared__ float sbias[NKEEP];

    const int tid  = threadIdx.x;
    const int lane = tid & 31;
    const int wid  = tid >> 5;
    const int wm   = wid & 1;
    const int wn   = wid >> 1;
    const int t = blockIdx.x;
    const int b = blockIdx.y;

    if (tid < NKEEP) sbias[tid] = cb[g_idx[b * NKEEP + tid]];

    const int r    = tid >> 1;
    const int half = tid & 1;
    const int s_st = t * 128 + r;
    const int hh = s_st / WW;
    const int ww = s_st % WW;
    const float* bsrc0 = g_bw + ((size_t)(b * NKEEP + r)) * 576 + half * 16;
    const float* abase = g_xt + (((size_t)b * SPAT) << 6) + half * 16;

    uint32_t smem_base = (uint32_t)__cvta_generic_to_shared(dyn);
    const uint32_t dstA0 = smem_base + (r * ASTRIDE + half * 16) * 4;
    const uint32_t dstB0 = smem_base + (128 * ASTRIDE + r * ASTRIDE + half * 16) * 4;
    const uint32_t stageB = 2 * 128 * ASTRIDE * 4;

    auto issue_chunk = [&](int kc, int p) {
        const int tap = kc >> 1;
        const int hc  = kc & 1;
        const int hp = hh + tap / 3 - 1;
        const int wp = ww + tap % 3 - 1;
        const bool valid = (s_st < SPAT) && ((unsigned)hp < (unsigned)HH) &&
                           ((unsigned)wp < (unsigned)WW);
        const uint32_t sz = valid ? 16u : 0u;
        int off = valid ? (hp * WW + wp) : 0;
        const float* asrc = abase + (((size_t)off) << 6) + hc * 32;
        const float* bsrc = bsrc0 + kc * 32;
        const uint32_t dA = dstA0 + p * stageB;
        const uint32_t dB = dstB0 + p * stageB;
#pragma unroll
        for (int j = 0; j < 4; j++) cp16(dA + j * 16, asrc + j * 4, sz);
#pragma unroll
        for (int j = 0; j < 4; j++) cp16(dB + j * 16, bsrc + j * 4, 16u);
        CP_COMMIT();
    };

    float acc[4][4][4];
#pragma unroll
    for (int mt = 0; mt < 4; mt++)
#pragma unroll
        for (int nt = 0; nt < 4; nt++)
#pragma unroll
            for (int c = 0; c < 4; c++) acc[mt][nt][c] = 0.f;

    const int lr = lane >> 2;
    const int lc = lane & 3;
    const float* sAf = dyn;
    const float* sBf = dyn + 128 * ASTRIDE;
    const int aRow0 = wm * 64 + lr;
    const int bRow0 = wn * 32 + lr;

    issue_chunk(0, 0);

#pragma unroll 1
    for (int kc = 0; kc < KCHUNKS; kc++) {
        const int p = kc & 1;
        CP_WAIT0();
        __syncthreads();
        if (kc + 1 < KCHUNKS) issue_chunk(kc + 1, p ^ 1);

        const float* A = sAf + p * 2 * 128 * ASTRIDE;
        const float* B = sBf + p * 2 * 128 * ASTRIDE;
#pragma unroll
        for (int k8 = 0; k8 < 4; k8++) {
            const int k0 = k8 * 8 + lc;
            uint32_t af[4][4];
#pragma unroll
            for (int mt = 0; mt < 4; mt++) {
                const float* ap = A + (aRow0 + mt * 16) * ASTRIDE + k0;
                af[mt][0] = __float_as_uint(ap[0]);
                af[mt][1] = __float_as_uint(ap[8 * ASTRIDE]);
                af[mt][2] = __float_as_uint(ap[4]);
                af[mt][3] = __float_as_uint(ap[8 * ASTRIDE + 4]);
            }
            uint32_t bf[4][2];
#pragma unroll
            for (int nt = 0; nt < 4; nt++) {
                const float* bp = B + (bRow0 + nt * 8) * ASTRIDE + k0;
                bf[nt][0] = __float_as_uint(bp[0]);
                bf[nt][1] = __float_as_uint(bp[4]);
            }
#pragma unroll
            for (int mt = 0; mt < 4; mt++)
#pragma unroll
                for (int nt = 0; nt < 4; nt++)
                    mma_tf32(acc[mt][nt], af[mt], bf[nt]);
        }
    }

    const int row0 = lane >> 2;
    const int col0 = (lane & 3) * 2;
#pragma unroll
    for (int mt = 0; mt < 4; mt++) {
#pragma unroll
        for (int nt = 0; nt < 4; nt++) {
            int n  = wn * 32 + nt * 8 + col0;
            int sr = t * 128 + wm * 64 + mt * 16 + row0;
            float b0 = sbias[n], b1 = sbias[n + 1];
            float* op0 = out + ((size_t)b * NKEEP + n) * SPAT;
            float* op1 = op0 + SPAT;
            if (sr < SPAT) {
                op0[sr] = acc[mt][nt][0] + b0;
                op1[sr] = acc[mt][nt][1] + b1;
            }
            if (sr + 8 < SPAT) {
                op0[sr + 8] = acc[mt][nt][2] + b0;
                op1[sr + 8] = acc[mt][nt][3] + b1;
            }
        }
    }
}

// ---------------------------------------------------------------------------
extern "C" void kernel_launch(void* const* d_in, const int* in_sizes, int n_in,
                              void* d_out, int out_size) {
    const float* x  = (const float*)d_in[0];   // [64,64,56,56]
    const float* cw = (const float*)d_in[1];   // [512,64,3,3]
    const float* cb = (const float*)d_in[2];   // [512]
    const float* rw = (const float*)d_in[3];   // [512,200704]
    const float* rb = (const float*)d_in[4];   // [512]
    float* out = (float*)d_out;                // [64,128,56,56]

    const int convsmem = 2 * 2 * 128 * ASTRIDE * 4;   // 73728 bytes
    const int rtsmem   = 2 * RSTAGE * 4;              // 55296 bytes
    cudaFuncSetAttribute(conv_mma, cudaFuncAttributeMaxDynamicSharedMemorySize, convsmem);
    cudaFuncSetAttribute(router_tc, cudaFuncAttributeMaxDynamicSharedMemorySize, rtsmem);

    transpose_x<<<dim3(SPAT / 32, CIN / 32, BB), dim3(32, 8)>>>(x);  // idx 0
    router_tc<<<dim3(CHN / 128, SPLITK), 256, rtsmem>>>(x, rw);       // idx 1
    fuse_select<<<BB, CHN>>>(rb, cw);                                 // idx 2
    conv_mma<<<dim3(NTILES, BB), 256, convsmem>>>(cb, out);           // idx 3 (profiled)
}

// round 10
// speedup vs baseline: 2.2858x; 1.0446x over previous
#include <cuda_runtime.h>
#include <cstdint>

#define BB    64
#define CIN   64
#define HH    56
#define WW    56
#define CHN   512
#define IN_DIM (CIN*HH*WW)      // 200704
#define NKEEP 128
#define SPLITK 112
#define KC (IN_DIM/SPLITK)      // 1792
#define SPAT (HH*WW)            // 3136
#define NTILES 25               // ceil(3136/128)
#define ASTRIDE 36              // router padded row stride (floats)
#define RKCH (KC/32)            // 56 router k-chunks per split
#define RSTAGE ((64+128)*ASTRIDE)   // router stage floats

#define CKCH 36                 // conv chunks: 9 taps * 4 ci-quarters of 16
#define CSTRIDE 20              // conv padded row stride (floats), conflict-free
#define CSTAGEF (256*CSTRIDE)   // conv stage floats (A 128 rows + B 128 rows)

// ---------------- small helpers ----------------
__device__ __forceinline__ float to_tf32(float f) {
    uint32_t u; asm("cvt.rna.tf32.f32 %0, %1;" : "=r"(u) : "f"(f));
    return __uint_as_float(u);
}
__device__ __forceinline__ void mma_tf32(float* c, const uint32_t* a, const uint32_t* b) {
    asm volatile(
        "mma.sync.aligned.m16n8k8.row.col.f32.tf32.tf32.f32 "
        "{%0,%1,%2,%3}, {%4,%5,%6,%7}, {%8,%9}, {%0,%1,%2,%3};"
        : "+f"(c[0]), "+f"(c[1]), "+f"(c[2]), "+f"(c[3])
        : "r"(a[0]), "r"(a[1]), "r"(a[2]), "r"(a[3]), "r"(b[0]), "r"(b[1]));
}
__device__ __forceinline__ void cp16(uint32_t dst_smem, const void* src, uint32_t srcsz) {
    asm volatile("cp.async.cg.shared.global [%0], [%1], 16, %2;"
                 :: "r"(dst_smem), "l"(src), "r"(srcsz));
}
#define CP_COMMIT() asm volatile("cp.async.commit_group;" ::: "memory")
#define CP_WAIT(n)  asm volatile("cp.async.wait_group %0;" :: "n"(n) : "memory")

// exact hi/lo split: hi is exactly tf32-representable, lo = v - hi exactly.
__device__ __forceinline__ void split_tf32(float v, uint32_t& hi, uint32_t& lo) {
    uint32_t u = __float_as_uint(v) & 0xFFFFE000u;
    hi = u;
    lo = __float_as_uint(v - __uint_as_float(u));
}

// ---------------- scratch ----------------
__device__ float g_partial[SPLITK * BB * CHN];  // 14.7 MB
__device__ int   g_idx[BB * NKEEP];
__device__ float g_xt[(size_t)BB * SPAT * CIN];   // x channels-last, tf32-rounded
__device__ float g_bw[(size_t)BB * NKEEP * 576];  // gathered weights [b][n][tap*64+ci]

// ---------------------------------------------------------------------------
// Kernel T (idx 0): transpose x to channels-last, rounding to tf32.
// ---------------------------------------------------------------------------
__global__ __launch_bounds__(256) void transpose_x(const float* __restrict__ x) {
    __shared__ float tile[32][33];
    const int s0 = blockIdx.x * 32;
    const int c0 = blockIdx.y * 32;
    const int b  = blockIdx.z;
    const int tx = threadIdx.x;
    const int ty = threadIdx.y;
#pragma unroll
    for (int k = 0; k < 4; k++) {
        int ci = c0 + ty + k * 8;
        tile[ty + k * 8][tx] = x[((size_t)b * CIN + ci) * SPAT + s0 + tx];
    }
    __syncthreads();
#pragma unroll
    for (int k = 0; k < 4; k++) {
        int srow = s0 + ty + k * 8;
        g_xt[((size_t)b * SPAT + srow) * CIN + c0 + tx] = to_tf32(tile[tx][ty + k * 8]);
    }
}

// ---------------------------------------------------------------------------
// Kernel 1 (idx 1): router GEMM partials on tensor cores, tf32x3.
// Block M=64 x N=128; 8 warps (2m x 4n). 3-stage cp.async pipeline,
// wait_group 1 -> 2 chunks in flight. Empty commits keep tail invariant.
// ---------------------------------------------------------------------------
__global__ __launch_bounds__(256) void router_tc(const float* __restrict__ x,
                                                 const float* __restrict__ rw) {
    extern __shared__ float rs[];   // [3][RSTAGE]

    const int ntile = blockIdx.x;    // 0..3
    const int sk    = blockIdx.y;    // 0..111
    const int tid  = threadIdx.x;
    const int lane = tid & 31;
    const int wid  = tid >> 5;
    const int wm   = wid & 1;
    const int wn   = wid >> 1;

    const int ar = tid >> 2, aq = tid & 3;
    const int br = tid >> 1, bh2 = tid & 1;
    const float* asrc0 = x  + (size_t)ar * IN_DIM + (size_t)sk * KC + aq * 8;
    const float* bsrc0 = rw + (size_t)(ntile * 128 + br) * IN_DIM + (size_t)sk * KC + bh2 * 16;
    const uint32_t base = (uint32_t)__cvta_generic_to_shared(rs);
    const uint32_t dstA = base + (ar * ASTRIDE + aq * 8) * 4;
    const uint32_t dstB = base + (64 * ASTRIDE + br * ASTRIDE + bh2 * 16) * 4;
    const uint32_t stageBytes = RSTAGE * 4;

    auto issue = [&](int kc, int p) {
        if (kc < RKCH) {
            const int k0 = kc * 32;
            const uint32_t dA = dstA + p * stageBytes;
            const uint32_t dB = dstB + p * stageBytes;
            cp16(dA,      asrc0 + k0,      16u);
            cp16(dA + 16, asrc0 + k0 + 4,  16u);
#pragma unroll
            for (int j = 0; j < 4; j++) cp16(dB + j * 16, bsrc0 + k0 + j * 4, 16u);
        }
        CP_COMMIT();   // empty group at tail keeps wait-count invariant
    };

    float acc[2][4][4];
#pragma unroll
    for (int mt = 0; mt < 2; mt++)
#pragma unroll
        for (int nt = 0; nt < 4; nt++)
#pragma unroll
            for (int c = 0; c < 4; c++) acc[mt][nt][c] = 0.f;

    const int lr = lane >> 2;
    const int lc = lane & 3;
    const int aRow0 = wm * 32 + lr;
    const int bRow0 = wn * 32 + lr;

    issue(0, 0);
    issue(1, 1);

    int ps = 0;          // compute stage
    int pn = 2;          // stage for chunk kc+2
#pragma unroll 1
    for (int kc = 0; kc < RKCH; kc++) {
        CP_WAIT(1);
        __syncthreads();
        issue(kc + 2, pn);

        const float* A = rs + ps * RSTAGE;
        const float* B = rs + ps * RSTAGE + 64 * ASTRIDE;
#pragma unroll
        for (int k8 = 0; k8 < 4; k8++) {
            const int k0 = k8 * 8 + lc;
            uint32_t ah[2][4], al[2][4];
#pragma unroll
            for (int mt = 0; mt < 2; mt++) {
                const float* ap = A + (aRow0 + mt * 16) * ASTRIDE + k0;
                split_tf32(ap[0],               ah[mt][0], al[mt][0]);
                split_tf32(ap[8 * ASTRIDE],     ah[mt][1], al[mt][1]);
                split_tf32(ap[4],               ah[mt][2], al[mt][2]);
                split_tf32(ap[8 * ASTRIDE + 4], ah[mt][3], al[mt][3]);
            }
            uint32_t bh[4][2], bl[4][2];
#pragma unroll
            for (int nt = 0; nt < 4; nt++) {
                const float* bp = B + (bRow0 + nt * 8) * ASTRIDE + k0;
                split_tf32(bp[0], bh[nt][0], bl[nt][0]);
                split_tf32(bp[4], bh[nt][1], bl[nt][1]);
            }
#pragma unroll
            for (int mt = 0; mt < 2; mt++)
#pragma unroll
                for (int nt = 0; nt < 4; nt++) {
                    mma_tf32(acc[mt][nt], al[mt], bh[nt]);
                    mma_tf32(acc[mt][nt], ah[mt], bl[nt]);
                    mma_tf32(acc[mt][nt], ah[mt], bh[nt]);
                }
        }
        ps = (ps == 2) ? 0 : ps + 1;
        pn = (pn == 2) ? 0 : pn + 1;
    }

    const int row0 = lane >> 2;
    const int col0 = (lane & 3) * 2;
#pragma unroll
    for (int mt = 0; mt < 2; mt++) {
#pragma unroll
        for (int nt = 0; nt < 4; nt++) {
            int m = wm * 32 + mt * 16 + row0;
            int n = ntile * 128 + wn * 32 + nt * 8 + col0;
            float* p0 = &g_partial[((size_t)sk * BB + m) * CHN + n];
            p0[0] = acc[mt][nt][0];
            p0[1] = acc[mt][nt][1];
            float* p1 = p0 + 8 * CHN;
            p1[0] = acc[mt][nt][2];
            p1[1] = acc[mt][nt][3];
        }
    }
}

// ---------------------------------------------------------------------------
// Kernel 2 (idx 2): FUSED reduce + stable top-128 + weight gather.
// ---------------------------------------------------------------------------
__global__ __launch_bounds__(CHN) void fuse_select(const float* __restrict__ rb,
                                                   const float* __restrict__ cw) {
    __shared__ float sa[CHN];
    __shared__ unsigned char keep[CHN];
    __shared__ int sidx[NKEEP];
    const int m = blockIdx.x;
    const int i = threadIdx.x;

    float sum = rb[i];
#pragma unroll 8
    for (int s = 0; s < SPLITK; s++)
        sum += g_partial[((size_t)s * BB + m) * CHN + i];

    float v = fabsf(sum);
    sa[i] = v;
    __syncthreads();
    int rank = 0;
    for (int j = 0; j < CHN; j++) {
        float u = sa[j];
        rank += (u > v) || (u == v && j < i);
    }
    keep[i] = (rank < NKEEP) ? 1 : 0;
    __syncthreads();
    if (keep[i]) {
        int pos = 0;
        for (int j = 0; j < i; j++) pos += keep[j];
        sidx[pos] = i;
        g_idx[m * NKEEP + pos] = i;
    }
    __syncthreads();

    for (int t = i; t < NKEEP * 576; t += CHN) {
        int n  = t / 576;
        int kk = t - n * 576;
        int c  = sidx[n];
        g_bw[((size_t)(m * NKEEP + n)) * 576 + kk] =
            to_tf32(cw[(size_t)c * 576 + (kk & 63) * 9 + (kk >> 6)]);
    }
}

// ---------------------------------------------------------------------------
// Kernel 4 (idx 3, profiled): conv implicit GEMM, tf32 m16n8k8.
// 4-stage cp.async pipeline, K=16 chunks (36), wait_group 2 -> 3 in flight.
// ---------------------------------------------------------------------------
__global__ __launch_bounds__(256, 2) void conv_mma(const float* __restrict__ cb,
                                                   float* __restrict__ out) {
    extern __shared__ float dyn[];   // [4][CSTAGEF]
    __shared__ float sbias[NKEEP];

    const int tid  = threadIdx.x;
    const int lane = tid & 31;
    const int wid  = tid >> 5;
    const int wm   = wid & 1;
    const int wn   = wid >> 1;
    const int t = blockIdx.x;
    const int b = blockIdx.y;

    if (tid < NKEEP) sbias[tid] = cb[g_idx[b * NKEEP + tid]];

    // staging: row r (0..127), half h (0/1) of the 16-float k-chunk
    const int r = tid >> 1;
    const int h = tid & 1;
    const int s_st = t * 128 + r;
    const int hh = s_st / WW;
    const int ww = s_st % WW;
    const float* bsrc0 = g_bw + ((size_t)(b * NKEEP + r)) * 576 + h * 8;
    const float* abase = g_xt + (((size_t)b * SPAT) << 6) + h * 8;

    uint32_t smem_base = (uint32_t)__cvta_generic_to_shared(dyn);
    const uint32_t dstA0 = smem_base + (r * CSTRIDE + h * 8) * 4;
    const uint32_t dstB0 = smem_base + (128 * CSTRIDE + r * CSTRIDE + h * 8) * 4;
    const uint32_t stageB = CSTAGEF * 4;

    auto issue_chunk = [&](int kc, int p) {
        if (kc < CKCH) {
            const int tap = kc >> 2;
            const int q   = kc & 3;
            const int hp = hh + tap / 3 - 1;
            const int wp = ww + tap % 3 - 1;
            const bool valid = (s_st < SPAT) && ((unsigned)hp < (unsigned)HH) &&
                               ((unsigned)wp < (unsigned)WW);
            const uint32_t sz = valid ? 16u : 0u;
            int off = valid ? (hp * WW + wp) : 0;
            const float* asrc = abase + (((size_t)off) << 6) + q * 16;
            const float* bsrc = bsrc0 + kc * 16;
            const uint32_t dA = dstA0 + p * stageB;
            const uint32_t dB = dstB0 + p * stageB;
            cp16(dA,      asrc,     sz);
            cp16(dA + 16, asrc + 4, sz);
            cp16(dB,      bsrc,     16u);
            cp16(dB + 16, bsrc + 4, 16u);
        }
        CP_COMMIT();
    };

    float acc[4][4][4];
#pragma unroll
    for (int mt = 0; mt < 4; mt++)
#pragma unroll
        for (int nt = 0; nt < 4; nt++)
#pragma unroll
            for (int c = 0; c < 4; c++) acc[mt][nt][c] = 0.f;

    const int lr = lane >> 2;
    const int lc = lane & 3;
    const int aRow0 = wm * 64 + lr;
    const int bRow0 = wn * 32 + lr;

    issue_chunk(0, 0);
    issue_chunk(1, 1);
    issue_chunk(2, 2);

#pragma unroll 1
    for (int kc = 0; kc < CKCH; kc++) {
        const int p = kc & 3;
        CP_WAIT(2);
        __syncthreads();
        issue_chunk(kc + 3, (kc + 3) & 3);

        const float* A = dyn + p * CSTAGEF;
        const float* B = dyn + p * CSTAGEF + 128 * CSTRIDE;
#pragma unroll
        for (int k8 = 0; k8 < 2; k8++) {
            const int k0 = k8 * 8 + lc;
            uint32_t af[4][4];
#pragma unroll
            for (int mt = 0; mt < 4; mt++) {
                const float* ap = A + (aRow0 + mt * 16) * CSTRIDE + k0;
                af[mt][0] = __float_as_uint(ap[0]);
                af[mt][1] = __float_as_uint(ap[8 * CSTRIDE]);
                af[mt][2] = __float_as_uint(ap[4]);
                af[mt][3] = __float_as_uint(ap[8 * CSTRIDE + 4]);
            }
            uint32_t bf[4][2];
#pragma unroll
            for (int nt = 0; nt < 4; nt++) {
                const float* bp = B + (bRow0 + nt * 8) * CSTRIDE + k0;
                bf[nt][0] = __float_as_uint(bp[0]);
                bf[nt][1] = __float_as_uint(bp[4]);
            }
#pragma unroll
            for (int mt = 0; mt < 4; mt++)
#pragma unroll
                for (int nt = 0; nt < 4; nt++)
                    mma_tf32(acc[mt][nt], af[mt], bf[nt]);
        }
    }

    const int row0 = lane >> 2;
    const int col0 = (lane & 3) * 2;
#pragma unroll
    for (int mt = 0; mt < 4; mt++) {
#pragma unroll
        for (int nt = 0; nt < 4; nt++) {
            int n  = wn * 32 + nt * 8 + col0;
            int sr = t * 128 + wm * 64 + mt * 16 + row0;
            float b0 = sbias[n], b1 = sbias[n + 1];
            float* op0 = out + ((size_t)b * NKEEP + n) * SPAT;
            float* op1 = op0 + SPAT;
            if (sr < SPAT) {
                op0[sr] = acc[mt][nt][0] + b0;
                op1[sr] = acc[mt][nt][1] + b1;
            }
            if (sr + 8 < SPAT) {
                op0[sr + 8] = acc[mt][nt][2] + b0;
                op1[sr + 8] = acc[mt][nt][3] + b1;
            }
        }
    }
}

// ---------------------------------------------------------------------------
extern "C" void kernel_launch(void* const* d_in, const int* in_sizes, int n_in,
                              void* d_out, int out_size) {
    const float* x  = (const float*)d_in[0];   // [64,64,56,56]
    const float* cw = (const float*)d_in[1];   // [512,64,3,3]
    const float* cb = (const float*)d_in[2];   // [512]
    const float* rw = (const float*)d_in[3];   // [512,200704]
    const float* rb = (const float*)d_in[4];   // [512]
    float* out = (float*)d_out;                // [64,128,56,56]

    const int convsmem = 4 * CSTAGEF * 4;      // 81920 bytes
    const int rtsmem   = 3 * RSTAGE * 4;       // 82944 bytes
    cudaFuncSetAttribute(conv_mma, cudaFuncAttributeMaxDynamicSharedMemorySize, convsmem);
    cudaFuncSetAttribute(router_tc, cudaFuncAttributeMaxDynamicSharedMemorySize, rtsmem);

    transpose_x<<<dim3(SPAT / 32, CIN / 32, BB), dim3(32, 8)>>>(x);  // idx 0
    router_tc<<<dim3(CHN / 128, SPLITK), 256, rtsmem>>>(x, rw);       // idx 1
    fuse_select<<<BB, CHN>>>(rb, cw);                                 // idx 2
    conv_mma<<<dim3(NTILES, BB), 256, convsmem>>>(cb, out);           // idx 3 (profiled)
}